// round 15
// baseline (speedup 1.0000x reference)
#include <cuda_runtime.h>
#include <cuda_bf16.h>
#include <math.h>
#include <cstdint>

#define B 8
#define M 64
#define D 256
#define NN 16384

// ========================= warp-MMA helpers (sm_80+ PTX, no arch suffix) ====
__device__ __forceinline__ uint32_t smem_to_u32(const void* p) {
    uint32_t a;
    asm("{ .reg .u64 t; cvta.to.shared.u64 t, %1; cvt.u32.u64 %0, t; }"
        : "=r"(a) : "l"(p));
    return a;
}
__device__ __forceinline__ void ldsm4(uint32_t* r, uint32_t addr) {
    asm volatile("ldmatrix.sync.aligned.m8n8.x4.shared.b16 {%0,%1,%2,%3}, [%4];"
        : "=r"(r[0]), "=r"(r[1]), "=r"(r[2]), "=r"(r[3]) : "r"(addr));
}
__device__ __forceinline__ void ldsm4t(uint32_t* r, uint32_t addr) {
    asm volatile("ldmatrix.sync.aligned.m8n8.x4.trans.shared.b16 {%0,%1,%2,%3}, [%4];"
        : "=r"(r[0]), "=r"(r[1]), "=r"(r[2]), "=r"(r[3]) : "r"(addr));
}
__device__ __forceinline__ void mma16816(float* c, const uint32_t* a, const uint32_t* b) {
    asm volatile("mma.sync.aligned.m16n8k16.row.col.f32.bf16.bf16.f32 "
        "{%0,%1,%2,%3}, {%4,%5,%6,%7}, {%8,%9}, {%0,%1,%2,%3};"
        : "+f"(c[0]), "+f"(c[1]), "+f"(c[2]), "+f"(c[3])
        : "r"(a[0]), "r"(a[1]), "r"(a[2]), "r"(a[3]), "r"(b[0]), "r"(b[1]));
}
// fast hi/lo split: 2 floats -> packed bf16x2 hi + packed bf16x2 lo
__device__ __forceinline__ void split2f(float v0, float v1, uint32_t& h, uint32_t& l) {
    uint32_t hh;
    asm("cvt.rn.bf16x2.f32 %0, %1, %2;" : "=r"(hh) : "f"(v1), "f"(v0));
    float h0 = __int_as_float(hh << 16);
    float h1 = __int_as_float(hh & 0xFFFF0000u);
    float l0 = v0 - h0, l1 = v1 - h1;
    uint32_t ll;
    asm("cvt.rn.bf16x2.f32 %0, %1, %2;" : "=r"(ll) : "f"(l1), "f"(l0));
    h = hh; l = ll;
}

// ========================= scratch globals =========================
__device__ float g_c[B*M*D];
__device__ float g_vc[B*M*D];
__device__ __nv_bfloat16 g_cn_hi[B*M*D];            // alpha-folded cnorm hi
__device__ __nv_bfloat16 g_cn_lo[B*M*D];
__device__ __nv_bfloat16 g_ass_hi[(size_t)B*M*NN];
__device__ __nv_bfloat16 g_ass_lo[(size_t)B*M*NN];
__device__ float g_colsum[B*M];
#define AV_SPLITS 32
__device__ float g_agg[B*M*D];                      // L2-resident accumulator
__device__ __nv_bfloat16 g_aggT_hi[B*D*M];          // agg^T [b][d][m]
__device__ __nv_bfloat16 g_aggT_lo[B*D*M];

// ---------------------------------------------------------------------------
__global__ void k_init() {
    int idx = blockIdx.x * 256 + threadIdx.x;
    if (idx < B*M*D) g_agg[idx] = 0.f;
    if (idx < B*M)   g_colsum[idx] = 0.f;
}

// ---------------------------------------------------------------------------
__global__ void __launch_bounds__(256) k_prep(
    const float* __restrict__ clusters, const float* __restrict__ cbias,
    const float* __restrict__ Wc, const float* __restrict__ bc,
    const float* __restrict__ vclusters, const float* __restrict__ vbias,
    const float* __restrict__ Wv, const float* __restrict__ bv)
{
    __shared__ float As[64][33];
    __shared__ float Ws[64][33];
    int which = blockIdx.z;
    const float* src   = which ? vclusters : clusters;
    const float* sbias = which ? vbias     : cbias;
    const float* Wp    = which ? Wv        : Wc;
    const float* bo    = which ? bv        : bc;
    float* out         = which ? g_vc      : g_c;

    int r0 = blockIdx.y * 64;
    int t0 = blockIdx.x * 64;
    int tid = threadIdx.x;
    int tx = tid & 15, ty = tid >> 4;

    float acc[4][4] = {};
    for (int k0 = 0; k0 < D; k0 += 32) {
        #pragma unroll
        for (int r = 0; r < 8; r++) {
            int idx = tid + 256*r;
            int row = idx >> 5, kk = idx & 31;
            As[row][kk] = src[(r0+row)*D + k0 + kk] + sbias[row*D + k0 + kk];
            Ws[row][kk] = Wp[(t0+row)*D + k0 + kk];
        }
        __syncthreads();
        #pragma unroll
        for (int k = 0; k < 32; k++) {
            float a[4], w[4];
            #pragma unroll
            for (int i = 0; i < 4; i++) a[i] = As[ty*4+i][k];
            #pragma unroll
            for (int j = 0; j < 4; j++) w[j] = Ws[tx*4+j][k];
            #pragma unroll
            for (int i = 0; i < 4; i++)
                #pragma unroll
                for (int j = 0; j < 4; j++) acc[i][j] += a[i]*w[j];
        }
        __syncthreads();
    }
    #pragma unroll
    for (int i = 0; i < 4; i++)
        #pragma unroll
        for (int j = 0; j < 4; j++) {
            int t = t0 + tx*4 + j;
            float s = acc[i][j] + bo[t];
            out[(r0 + ty*4 + i)*D + t] = s / (1.f + __expf(-s));
        }
}

// ---------------------------------------------------------------------------
// l2norm rows of g_c, fold alpha, emit bf16 hi/lo
__global__ void __launch_bounds__(256) k_norm(const float* __restrict__ alpha) {
    int r = blockIdx.x;
    int tid = threadIdx.x;
    float v = g_c[r*D + tid];
    float s = v*v;
    #pragma unroll
    for (int o = 16; o > 0; o >>= 1) s += __shfl_xor_sync(0xffffffffu, s, o);
    __shared__ float ws[8];
    if ((tid & 31) == 0) ws[tid >> 5] = s;
    __syncthreads();
    float tot = 0.f;
    #pragma unroll
    for (int w = 0; w < 8; w++) tot += ws[w];
    float inv = alpha[r & 63] / fmaxf(sqrtf(tot), 1e-12f);
    float val = v * inv;
    __nv_bfloat16 h = __float2bfloat16(val);
    g_cn_hi[r*D + tid] = h;
    g_cn_lo[r*D + tid] = __float2bfloat16(val - __bfloat162float(h));
}

// ---------------------------------------------------------------------------
// k_sim: HMMA, 4 CTAs/SM (R13/R14 measured: 67us, occ 46%). FROZEN.
#define SIM_AH 0        // [64][72] bf16 = 9216
#define SIM_AL 9216
#define SIM_BH 18432    // [64][136] bf16 = 17408
#define SIM_BL 35840
#define SIM_PINV 53248  // 128 f32 (atomic ss accum -> rsqrt)
#define SIM_RED 53760   // 2*128 f32
#define SIM_BET 54784   // 64 f32
#define SIM_SMEM 55040
__global__ void __launch_bounds__(256, 4) k_sim(
    const float* __restrict__ points, const float* __restrict__ beta)
{
    extern __shared__ char dsm[];
    const int tid = threadIdx.x, lane = tid & 31, w = tid >> 5;
    const int b = blockIdx.y, n0 = blockIdx.x * 128;
    uint32_t sb = smem_to_u32(dsm);

    float* pinv = (float*)(dsm + SIM_PINV);
    float* red  = (float*)(dsm + SIM_RED);
    float* sbet = (float*)(dsm + SIM_BET);
    if (tid < 128) pinv[tid] = 0.f;
    if (tid < 64)  sbet[tid] = beta[tid];

    const __nv_bfloat16* ch = g_cn_hi + b*M*D;
    const __nv_bfloat16* cl = g_cn_lo + b*M*D;
    const float* pp = points + (size_t)b*D*NN;

    const int m0 = 16*(w & 3);
    const int nh = w >> 2;

    const int ar = tid >> 3, as8 = (tid & 7)*8;      // A copy: row ar(+32), col as8
    const int bk = tid >> 5, bn = 4*(tid & 31);      // B: row r*8+bk

    float C[8][4] = {};
    float ss[4] = {0.f, 0.f, 0.f, 0.f};

    #pragma unroll
    for (int ci = 0; ci < 4; ci++) {
        int k0 = ci * 64;
        __syncthreads();   // prior MMA done reading smem (also orders pinv init)
        #pragma unroll
        for (int r = 0; r < 2; r++) {
            int row = r*32 + ar;
            *(uint4*)(dsm + SIM_AH + (row*72 + as8)*2) =
                *(const uint4*)&ch[row*256 + k0 + as8];
            *(uint4*)(dsm + SIM_AL + (row*72 + as8)*2) =
                *(const uint4*)&cl[row*256 + k0 + as8];
        }
        #pragma unroll
        for (int r = 0; r < 8; r++) {
            int k = r*8 + bk;
            float4 v = *(const float4*)&pp[(size_t)(k0+k)*NN + n0 + bn];
            ss[0] += v.x*v.x; ss[1] += v.y*v.y; ss[2] += v.z*v.z; ss[3] += v.w*v.w;
            uint32_t h0, l0, h1, l1;
            split2f(v.x, v.y, h0, l0);
            split2f(v.z, v.w, h1, l1);
            *(uint2*)(dsm + SIM_BH + (k*136 + bn)*2) = make_uint2(h0, h1);
            *(uint2*)(dsm + SIM_BL + (k*136 + bn)*2) = make_uint2(l0, l1);
        }
        __syncthreads();
        #pragma unroll
        for (int ks = 0; ks < 4; ks++) {
            uint32_t ah[4], al[4];
            uint32_t aoff = ((m0 + (lane & 15))*72 + ks*16 + 8*(lane >> 4))*2;
            ldsm4(ah, sb + SIM_AH + aoff);
            ldsm4(al, sb + SIM_AL + aoff);
            #pragma unroll
            for (int g = 0; g < 4; g++) {
                uint32_t bh[4], bl[4];
                uint32_t boff = ((ks*16 + (lane & 15))*136 + nh*64 + g*16 + 8*(lane >> 4))*2;
                ldsm4t(bh, sb + SIM_BH + boff);
                ldsm4t(bl, sb + SIM_BL + boff);
                mma16816(C[2*g],   ah, bh);
                mma16816(C[2*g],   al, bh);
                mma16816(C[2*g],   ah, bl);
                mma16816(C[2*g+1], ah, bh+2);
                mma16816(C[2*g+1], al, bh+2);
                mma16816(C[2*g+1], ah, bl+2);
            }
        }
    }
    __syncthreads();

    // sum-of-squares: 8 warps atomically accumulate into pinv[128]
    #pragma unroll
    for (int u = 0; u < 4; u++) atomicAdd(&pinv[4*(tid & 31) + u], ss[u]);

    float* Cs = (float*)dsm;   // [64][132]
    #pragma unroll
    for (int f = 0; f < 8; f++) {
        int col = nh*64 + (f>>1)*16 + (f&1)*8 + 2*(lane & 3);
        int row = m0 + (lane >> 2);
        Cs[row*132 + col]     = C[f][0];
        Cs[row*132 + col + 1] = C[f][1];
        Cs[(row+8)*132 + col]     = C[f][2];
        Cs[(row+8)*132 + col + 1] = C[f][3];
    }
    __syncthreads();

    if (tid < 128) pinv[tid] = 1.f / fmaxf(sqrtf(pinv[tid]), 1e-12f);
    __syncthreads();

    int c = tid & 127, h = tid >> 7;
    float pv = pinv[c];
    float v[32];
    float mx = -1e30f;
    #pragma unroll
    for (int r = 0; r < 32; r++) {
        int m = h*32 + r;
        v[r] = Cs[m*132 + c] * pv + sbet[m];
        mx = fmaxf(mx, v[r]);
    }
    red[h*128 + c] = mx;
    __syncthreads();
    float gmx = fmaxf(red[c], red[128 + c]);
    __syncthreads();
    float lsum = 0.f;
    #pragma unroll
    for (int r = 0; r < 32; r++) {
        v[r] = __expf(v[r] - gmx);
        lsum += v[r];
    }
    red[h*128 + c] = lsum;
    __syncthreads();
    float inv = 1.f / (red[c] + red[128 + c]);

    #pragma unroll
    for (int r = 0; r < 32; r++)
        Cs[(h*32 + r)*132 + c] = v[r] * inv;
    __syncthreads();

    // colsum: row = tid>>2, quarter q = tid&3 (32 cols each)
    {
        int row = tid >> 2, q = tid & 3;
        float s = 0.f;
        #pragma unroll
        for (int j = 0; j < 32; j++) s += Cs[row*132 + q*32 + j];
        s += __shfl_xor_sync(0xffffffffu, s, 1);
        s += __shfl_xor_sync(0xffffffffu, s, 2);
        if (q == 0) atomicAdd(&g_colsum[b*64 + row], s);
    }

    __nv_bfloat16* ahp = g_ass_hi + (size_t)b*M*NN;
    __nv_bfloat16* alp = g_ass_lo + (size_t)b*M*NN;
    #pragma unroll
    for (int r = 0; r < 16; r++) {
        int idx = r*256 + tid;
        int m = idx >> 6, c2 = (idx & 63)*2;
        uint32_t hh, ll;
        split2f(Cs[m*132 + c2], Cs[m*132 + c2 + 1], hh, ll);
        *(uint32_t*)&ahp[(size_t)m*NN + n0 + c2] = hh;
        *(uint32_t*)&alp[(size_t)m*NN + n0 + c2] = ll;
    }
}

// ---------------------------------------------------------------------------
// k_av: HMMA, halved B staging (rb[4], two phases) -> ~79 live regs, 3 CTAs/SM.
// Atomic accumulation into g_agg. grid (2 dt, 32 s, 8 b).
#define AV_AH 0         // [64][72] bf16
#define AV_AL 9216
#define AV_BH 18432     // [64][136] bf16
#define AV_BL 35840
#define AV_SMEM 53248
__global__ void __launch_bounds__(256, 3) k_av(const float* __restrict__ values) {
    extern __shared__ char dsm[];
    const int tid = threadIdx.x, lane = tid & 31, w = tid >> 5;
    const int dt = blockIdx.x, s = blockIdx.y, b = blockIdx.z;
    const int nb = s * 512, d0t = dt * 128;
    uint32_t sb = smem_to_u32(dsm);

    const __nv_bfloat16* ahp = g_ass_hi + (size_t)b*M*NN;
    const __nv_bfloat16* alp = g_ass_lo + (size_t)b*M*NN;
    const float* vp = values + (size_t)b*NN*D;

    const int m0 = 16*(w & 3);
    const int dh = w >> 2;

    const int am = tid >> 3, ak8 = (tid & 7)*8;      // A: row r*32+am
    const int bk = tid >> 5, bd = 4*(tid & 31);      // B: row r*8+bk

    float C[8][4] = {};
    uint4 rah[2], ral[2];
    float4 rb[4];

    // prefetch chunk 0 (A full, B rows 0-3)
    #pragma unroll
    for (int r = 0; r < 2; r++) {
        rah[r] = *(const uint4*)&ahp[(size_t)(r*32 + am)*NN + nb + ak8];
        ral[r] = *(const uint4*)&alp[(size_t)(r*32 + am)*NN + nb + ak8];
    }
    #pragma unroll
    for (int r = 0; r < 4; r++)
        rb[r] = *(const float4*)&vp[(size_t)(nb + r*8 + bk)*D + d0t + bd];

    for (int ci = 0; ci < 8; ci++) {
        int nk = nb + ci*64;
        __syncthreads();
        #pragma unroll
        for (int r = 0; r < 2; r++) {
            *(uint4*)(dsm + AV_AH + ((r*32 + am)*72 + ak8)*2) = rah[r];
            *(uint4*)(dsm + AV_AL + ((r*32 + am)*72 + ak8)*2) = ral[r];
        }
        // phase 1: store staged B rows 0-3, stage rows 4-7
        #pragma unroll
        for (int r = 0; r < 4; r++) {
            float4 v = rb[r];
            uint32_t h0, l0, h1, l1;
            split2f(v.x, v.y, h0, l0);
            split2f(v.z, v.w, h1, l1);
            *(uint2*)(dsm + AV_BH + ((r*8 + bk)*136 + bd)*2) = make_uint2(h0, h1);
            *(uint2*)(dsm + AV_BL + ((r*8 + bk)*136 + bd)*2) = make_uint2(l0, l1);
        }
        #pragma unroll
        for (int r = 0; r < 4; r++)
            rb[r] = *(const float4*)&vp[(size_t)(nk + (r+4)*8 + bk)*D + d0t + bd];
        // phase 2: store B rows 4-7
        #pragma unroll
        for (int r = 0; r < 4; r++) {
            float4 v = rb[r];
            uint32_t h0, l0, h1, l1;
            split2f(v.x, v.y, h0, l0);
            split2f(v.z, v.w, h1, l1);
            *(uint2*)(dsm + AV_BH + (((r+4)*8 + bk)*136 + bd)*2) = make_uint2(h0, h1);
            *(uint2*)(dsm + AV_BL + (((r+4)*8 + bk)*136 + bd)*2) = make_uint2(l0, l1);
        }
        __syncthreads();
        if (ci < 7) {   // prefetch next chunk (A full, B rows 0-3)
            int nk1 = nk + 64;
            #pragma unroll
            for (int r = 0; r < 2; r++) {
                rah[r] = *(const uint4*)&ahp[(size_t)(r*32 + am)*NN + nk1 + ak8];
                ral[r] = *(const uint4*)&alp[(size_t)(r*32 + am)*NN + nk1 + ak8];
            }
            #pragma unroll
            for (int r = 0; r < 4; r++)
                rb[r] = *(const float4*)&vp[(size_t)(nk1 + r*8 + bk)*D + d0t + bd];
        }
        #pragma unroll
        for (int ks = 0; ks < 4; ks++) {
            uint32_t ah[4], al[4];
            uint32_t aoff = ((m0 + (lane & 15))*72 + ks*16 + 8*(lane >> 4))*2;
            ldsm4(ah, sb + AV_AH + aoff);
            ldsm4(al, sb + AV_AL + aoff);
            #pragma unroll
            for (int g = 0; g < 4; g++) {
                uint32_t bh[4], bl[4];
                uint32_t boff = ((ks*16 + (lane & 15))*136 + dh*64 + g*16 + 8*(lane >> 4))*2;
                ldsm4t(bh, sb + AV_BH + boff);
                ldsm4t(bl, sb + AV_BL + boff);
                mma16816(C[2*g],   ah, bh);
                mma16816(C[2*g],   al, bh);
                mma16816(C[2*g],   ah, bl);
                mma16816(C[2*g+1], ah, bh+2);
                mma16816(C[2*g+1], al, bh+2);
                mma16816(C[2*g+1], ah, bl+2);
            }
        }
    }
    float* op = g_agg + (size_t)b*M*D;
    #pragma unroll
    for (int f = 0; f < 8; f++) {
        int col = d0t + dh*64 + (f>>1)*16 + (f&1)*8 + 2*(lane & 3);
        int row = m0 + (lane >> 2);
        atomicAdd(&op[row*256 + col],     C[f][0]);
        atomicAdd(&op[row*256 + col + 1], C[f][1]);
        atomicAdd(&op[(row+8)*256 + col],     C[f][2]);
        atomicAdd(&op[(row+8)*256 + col + 1], C[f][3]);
    }
}

// ---------------------------------------------------------------------------
__global__ void __launch_bounds__(256) k_agg() {
    int bm = blockIdx.x;
    int b = bm >> 6, m = bm & 63;
    int d = threadIdx.x;
    float val = (g_vc[bm*D + d] + g_agg[bm*D + d]) / (g_colsum[bm] + 1e-7f);
    __nv_bfloat16 h = __float2bfloat16(val);
    __nv_bfloat16 l = __float2bfloat16(val - __bfloat162float(h));
    g_aggT_hi[((size_t)b*D + d)*64 + m] = h;
    g_aggT_lo[((size_t)b*D + d)*64 + m] = l;
}

// ---------------------------------------------------------------------------
// k_x: HMMA. x[128d][128n] = aggT @ assign, K=64 single shot.
// Direct fragment stores (sector-aligned float2 quads) — no Cs staging.
// grid (2 dt, 128 n, 8 b).
#define X_AH 0          // [128][72] bf16 = 18432
#define X_AL 18432
#define X_BH 36864      // [64][136] bf16 = 17408
#define X_BL 54272
#define X_SMEM 71680
__global__ void __launch_bounds__(256) k_x(float* __restrict__ x) {
    extern __shared__ char dsm[];
    const int tid = threadIdx.x, lane = tid & 31, w = tid >> 5;
    const int d0 = blockIdx.x * 128, n0 = blockIdx.y * 128, b = blockIdx.z;
    uint32_t sb = smem_to_u32(dsm);

    #pragma unroll
    for (int r = 0; r < 4; r++) {
        int idx = r*256 + tid;
        int d = idx >> 3, m8 = (idx & 7)*8;
        size_t src = ((size_t)b*D + d0 + d)*64 + m8;
        *(uint4*)(dsm + X_AH + (d*72 + m8)*2) = *(const uint4*)&g_aggT_hi[src];
        *(uint4*)(dsm + X_AL + (d*72 + m8)*2) = *(const uint4*)&g_aggT_lo[src];
    }
    #pragma unroll
    for (int r = 0; r < 4; r++) {
        int idx = r*256 + tid;
        int m = idx >> 4, n8 = (idx & 15)*8;
        size_t src = (size_t)(b*M + m)*NN + n0 + n8;
        *(uint4*)(dsm + X_BH + (m*136 + n8)*2) = *(const uint4*)&g_ass_hi[src];
        *(uint4*)(dsm + X_BL + (m*136 + n8)*2) = *(const uint4*)&g_ass_lo[src];
    }
    __syncthreads();

    const int d0w = 16*w;
    float C[16][4] = {};
    #pragma unroll
    for (int ks = 0; ks < 4; ks++) {
        uint32_t ah[4], al[4];
        uint32_t aoff = ((d0w + (lane & 15))*72 + ks*16 + 8*(lane >> 4))*2;
        ldsm4(ah, sb + X_AH + aoff);
        ldsm4(al, sb + X_AL + aoff);
        #pragma unroll
        for (int g = 0; g < 8; g++) {
            uint32_t bh[4], bl[4];
            uint32_t boff = ((ks*16 + (lane & 15))*136 + g*16 + 8*(lane >> 4))*2;
            ldsm4t(bh, sb + X_BH + boff);
            ldsm4t(bl, sb + X_BL + boff);
            mma16816(C[2*g],   ah, bh);
            mma16816(C[2*g],   al, bh);
            mma16816(C[2*g],   ah, bl);
            mma16816(C[2*g+1], ah, bh+2);
            mma16816(C[2*g+1], al, bh+2);
            mma16816(C[2*g+1], ah, bl+2);
        }
    }

    // direct stores: each 4-lane quad writes 32B contiguous per row (full sector)
    #pragma unroll
    for (int f = 0; f < 16; f++) {
        int col = n0 + (f>>1)*16 + (f&1)*8 + 2*(lane & 3);
        int row = d0 + d0w + (lane >> 2);
        float* xp = x + (size_t)(b*D + row)*NN + col;
        *(float2*)xp = make_float2(C[f][0], C[f][1]);
        *(float2*)(xp + 8*NN) = make_float2(C[f][2], C[f][3]);
    }
}

// ---------------------------------------------------------------------------
extern "C" void kernel_launch(void* const* d_in, const int* in_sizes, int n_in,
                              void* d_out, int out_size) {
    const float* points    = (const float*)d_in[0];
    const float* clusters  = (const float*)d_in[1];
    const float* values    = (const float*)d_in[2];
    const float* vclusters = (const float*)d_in[3];
    const float* alpha     = (const float*)d_in[4];
    const float* beta      = (const float*)d_in[5];
    const float* cbias     = (const float*)d_in[6];
    const float* Wc        = (const float*)d_in[7];
    const float* bc        = (const float*)d_in[8];
    const float* vbias     = (const float*)d_in[9];
    const float* Wv        = (const float*)d_in[10];
    const float* bv        = (const float*)d_in[11];
    float* x = (float*)d_out;

    cudaFuncSetAttribute(k_sim, cudaFuncAttributeMaxDynamicSharedMemorySize, SIM_SMEM);
    cudaFuncSetAttribute(k_av,  cudaFuncAttributeMaxDynamicSharedMemorySize, AV_SMEM);
    cudaFuncSetAttribute(k_x,   cudaFuncAttributeMaxDynamicSharedMemorySize, X_SMEM);

    k_init<<<512, 256>>>();
    k_prep<<<dim3(4, 8, 2), 256>>>(clusters, cbias, Wc, bc,
                                   vclusters, vbias, Wv, bv);
    k_norm<<<512, 256>>>(alpha);
    k_sim<<<dim3(NN/128, B), 256, SIM_SMEM>>>(points, beta);
    k_av<<<dim3(2, AV_SPLITS, B), 256, AV_SMEM>>>(values);
    k_agg<<<512, 256>>>();
    k_x<<<dim3(2, NN/128, B), 256, X_SMEM>>>(x);
}

// round 16
// speedup vs baseline: 1.1478x; 1.1478x over previous
#include <cuda_runtime.h>
#include <cuda_bf16.h>
#include <math.h>
#include <cstdint>

#define B 8
#define M 64
#define D 256
#define NN 16384

// ========================= warp-MMA helpers (sm_80+ PTX, no arch suffix) ====
__device__ __forceinline__ uint32_t smem_to_u32(const void* p) {
    uint32_t a;
    asm("{ .reg .u64 t; cvta.to.shared.u64 t, %1; cvt.u32.u64 %0, t; }"
        : "=r"(a) : "l"(p));
    return a;
}
__device__ __forceinline__ void ldsm4(uint32_t* r, uint32_t addr) {
    asm volatile("ldmatrix.sync.aligned.m8n8.x4.shared.b16 {%0,%1,%2,%3}, [%4];"
        : "=r"(r[0]), "=r"(r[1]), "=r"(r[2]), "=r"(r[3]) : "r"(addr));
}
__device__ __forceinline__ void ldsm4t(uint32_t* r, uint32_t addr) {
    asm volatile("ldmatrix.sync.aligned.m8n8.x4.trans.shared.b16 {%0,%1,%2,%3}, [%4];"
        : "=r"(r[0]), "=r"(r[1]), "=r"(r[2]), "=r"(r[3]) : "r"(addr));
}
__device__ __forceinline__ void mma16816(float* c, const uint32_t* a, const uint32_t* b) {
    asm volatile("mma.sync.aligned.m16n8k16.row.col.f32.bf16.bf16.f32 "
        "{%0,%1,%2,%3}, {%4,%5,%6,%7}, {%8,%9}, {%0,%1,%2,%3};"
        : "+f"(c[0]), "+f"(c[1]), "+f"(c[2]), "+f"(c[3])
        : "r"(a[0]), "r"(a[1]), "r"(a[2]), "r"(a[3]), "r"(b[0]), "r"(b[1]));
}
// fast hi/lo split: 2 floats -> packed bf16x2 hi + packed bf16x2 lo
__device__ __forceinline__ void split2f(float v0, float v1, uint32_t& h, uint32_t& l) {
    uint32_t hh;
    asm("cvt.rn.bf16x2.f32 %0, %1, %2;" : "=r"(hh) : "f"(v1), "f"(v0));
    float h0 = __int_as_float(hh << 16);
    float h1 = __int_as_float(hh & 0xFFFF0000u);
    float l0 = v0 - h0, l1 = v1 - h1;
    uint32_t ll;
    asm("cvt.rn.bf16x2.f32 %0, %1, %2;" : "=r"(ll) : "f"(l1), "f"(l0));
    h = hh; l = ll;
}

// ========================= scratch globals =========================
__device__ float g_c[B*M*D];
__device__ float g_vc[B*M*D];
__device__ __nv_bfloat16 g_cn_hi[B*M*D];            // alpha-folded cnorm hi
__device__ __nv_bfloat16 g_cn_lo[B*M*D];
__device__ __nv_bfloat16 g_ass_hi[(size_t)B*M*NN];
__device__ __nv_bfloat16 g_ass_lo[(size_t)B*M*NN];
__device__ float g_colsum[B*M];
#define AV_SPLITS 32
__device__ float g_agg[B*M*D];                      // L2-resident accumulator
__device__ __nv_bfloat16 g_aggT_hi[B*D*M];          // agg^T [b][d][m]
__device__ __nv_bfloat16 g_aggT_lo[B*D*M];

// ---------------------------------------------------------------------------
__global__ void k_init() {
    int idx = blockIdx.x * 256 + threadIdx.x;
    if (idx < B*M*D) g_agg[idx] = 0.f;
    if (idx < B*M)   g_colsum[idx] = 0.f;
}

// ---------------------------------------------------------------------------
__global__ void __launch_bounds__(256) k_prep(
    const float* __restrict__ clusters, const float* __restrict__ cbias,
    const float* __restrict__ Wc, const float* __restrict__ bc,
    const float* __restrict__ vclusters, const float* __restrict__ vbias,
    const float* __restrict__ Wv, const float* __restrict__ bv)
{
    __shared__ float As[64][33];
    __shared__ float Ws[64][33];
    int which = blockIdx.z;
    const float* src   = which ? vclusters : clusters;
    const float* sbias = which ? vbias     : cbias;
    const float* Wp    = which ? Wv        : Wc;
    const float* bo    = which ? bv        : bc;
    float* out         = which ? g_vc      : g_c;

    int r0 = blockIdx.y * 64;
    int t0 = blockIdx.x * 64;
    int tid = threadIdx.x;
    int tx = tid & 15, ty = tid >> 4;

    float acc[4][4] = {};
    for (int k0 = 0; k0 < D; k0 += 32) {
        #pragma unroll
        for (int r = 0; r < 8; r++) {
            int idx = tid + 256*r;
            int row = idx >> 5, kk = idx & 31;
            As[row][kk] = src[(r0+row)*D + k0 + kk] + sbias[row*D + k0 + kk];
            Ws[row][kk] = Wp[(t0+row)*D + k0 + kk];
        }
        __syncthreads();
        #pragma unroll
        for (int k = 0; k < 32; k++) {
            float a[4], w[4];
            #pragma unroll
            for (int i = 0; i < 4; i++) a[i] = As[ty*4+i][k];
            #pragma unroll
            for (int j = 0; j < 4; j++) w[j] = Ws[tx*4+j][k];
            #pragma unroll
            for (int i = 0; i < 4; i++)
                #pragma unroll
                for (int j = 0; j < 4; j++) acc[i][j] += a[i]*w[j];
        }
        __syncthreads();
    }
    #pragma unroll
    for (int i = 0; i < 4; i++)
        #pragma unroll
        for (int j = 0; j < 4; j++) {
            int t = t0 + tx*4 + j;
            float s = acc[i][j] + bo[t];
            out[(r0 + ty*4 + i)*D + t] = s / (1.f + __expf(-s));
        }
}

// ---------------------------------------------------------------------------
// l2norm rows of g_c, fold alpha, emit bf16 hi/lo
__global__ void __launch_bounds__(256) k_norm(const float* __restrict__ alpha) {
    int r = blockIdx.x;
    int tid = threadIdx.x;
    float v = g_c[r*D + tid];
    float s = v*v;
    #pragma unroll
    for (int o = 16; o > 0; o >>= 1) s += __shfl_xor_sync(0xffffffffu, s, o);
    __shared__ float ws[8];
    if ((tid & 31) == 0) ws[tid >> 5] = s;
    __syncthreads();
    float tot = 0.f;
    #pragma unroll
    for (int w = 0; w < 8; w++) tot += ws[w];
    float inv = alpha[r & 63] / fmaxf(sqrtf(tot), 1e-12f);
    float val = v * inv;
    __nv_bfloat16 h = __float2bfloat16(val);
    g_cn_hi[r*D + tid] = h;
    g_cn_lo[r*D + tid] = __float2bfloat16(val - __bfloat162float(h));
}

// ---------------------------------------------------------------------------
// k_sim: HMMA, 4 CTAs/SM (R13/R14 measured: 67us, occ 46%). FROZEN.
#define SIM_AH 0        // [64][72] bf16 = 9216
#define SIM_AL 9216
#define SIM_BH 18432    // [64][136] bf16 = 17408
#define SIM_BL 35840
#define SIM_PINV 53248  // 128 f32 (atomic ss accum -> rsqrt)
#define SIM_RED 53760   // 2*128 f32
#define SIM_BET 54784   // 64 f32
#define SIM_SMEM 55040
__global__ void __launch_bounds__(256, 4) k_sim(
    const float* __restrict__ points, const float* __restrict__ beta)
{
    extern __shared__ char dsm[];
    const int tid = threadIdx.x, lane = tid & 31, w = tid >> 5;
    const int b = blockIdx.y, n0 = blockIdx.x * 128;
    uint32_t sb = smem_to_u32(dsm);

    float* pinv = (float*)(dsm + SIM_PINV);
    float* red  = (float*)(dsm + SIM_RED);
    float* sbet = (float*)(dsm + SIM_BET);
    if (tid < 128) pinv[tid] = 0.f;
    if (tid < 64)  sbet[tid] = beta[tid];

    const __nv_bfloat16* ch = g_cn_hi + b*M*D;
    const __nv_bfloat16* cl = g_cn_lo + b*M*D;
    const float* pp = points + (size_t)b*D*NN;

    const int m0 = 16*(w & 3);
    const int nh = w >> 2;

    const int ar = tid >> 3, as8 = (tid & 7)*8;      // A copy: row ar(+32), col as8
    const int bk = tid >> 5, bn = 4*(tid & 31);      // B: row r*8+bk

    float C[8][4] = {};
    float ss[4] = {0.f, 0.f, 0.f, 0.f};

    #pragma unroll
    for (int ci = 0; ci < 4; ci++) {
        int k0 = ci * 64;
        __syncthreads();   // prior MMA done reading smem (also orders pinv init)
        #pragma unroll
        for (int r = 0; r < 2; r++) {
            int row = r*32 + ar;
            *(uint4*)(dsm + SIM_AH + (row*72 + as8)*2) =
                *(const uint4*)&ch[row*256 + k0 + as8];
            *(uint4*)(dsm + SIM_AL + (row*72 + as8)*2) =
                *(const uint4*)&cl[row*256 + k0 + as8];
        }
        #pragma unroll
        for (int r = 0; r < 8; r++) {
            int k = r*8 + bk;
            float4 v = *(const float4*)&pp[(size_t)(k0+k)*NN + n0 + bn];
            ss[0] += v.x*v.x; ss[1] += v.y*v.y; ss[2] += v.z*v.z; ss[3] += v.w*v.w;
            uint32_t h0, l0, h1, l1;
            split2f(v.x, v.y, h0, l0);
            split2f(v.z, v.w, h1, l1);
            *(uint2*)(dsm + SIM_BH + (k*136 + bn)*2) = make_uint2(h0, h1);
            *(uint2*)(dsm + SIM_BL + (k*136 + bn)*2) = make_uint2(l0, l1);
        }
        __syncthreads();
        #pragma unroll
        for (int ks = 0; ks < 4; ks++) {
            uint32_t ah[4], al[4];
            uint32_t aoff = ((m0 + (lane & 15))*72 + ks*16 + 8*(lane >> 4))*2;
            ldsm4(ah, sb + SIM_AH + aoff);
            ldsm4(al, sb + SIM_AL + aoff);
            #pragma unroll
            for (int g = 0; g < 4; g++) {
                uint32_t bh[4], bl[4];
                uint32_t boff = ((ks*16 + (lane & 15))*136 + nh*64 + g*16 + 8*(lane >> 4))*2;
                ldsm4t(bh, sb + SIM_BH + boff);
                ldsm4t(bl, sb + SIM_BL + boff);
                mma16816(C[2*g],   ah, bh);
                mma16816(C[2*g],   al, bh);
                mma16816(C[2*g],   ah, bl);
                mma16816(C[2*g+1], ah, bh+2);
                mma16816(C[2*g+1], al, bh+2);
                mma16816(C[2*g+1], ah, bl+2);
            }
        }
    }
    __syncthreads();

    // sum-of-squares: 8 warps atomically accumulate into pinv[128]
    #pragma unroll
    for (int u = 0; u < 4; u++) atomicAdd(&pinv[4*(tid & 31) + u], ss[u]);

    float* Cs = (float*)dsm;   // [64][132]
    #pragma unroll
    for (int f = 0; f < 8; f++) {
        int col = nh*64 + (f>>1)*16 + (f&1)*8 + 2*(lane & 3);
        int row = m0 + (lane >> 2);
        Cs[row*132 + col]     = C[f][0];
        Cs[row*132 + col + 1] = C[f][1];
        Cs[(row+8)*132 + col]     = C[f][2];
        Cs[(row+8)*132 + col + 1] = C[f][3];
    }
    __syncthreads();

    if (tid < 128) pinv[tid] = 1.f / fmaxf(sqrtf(pinv[tid]), 1e-12f);
    __syncthreads();

    int c = tid & 127, h = tid >> 7;
    float pv = pinv[c];
    float v[32];
    float mx = -1e30f;
    #pragma unroll
    for (int r = 0; r < 32; r++) {
        int m = h*32 + r;
        v[r] = Cs[m*132 + c] * pv + sbet[m];
        mx = fmaxf(mx, v[r]);
    }
    red[h*128 + c] = mx;
    __syncthreads();
    float gmx = fmaxf(red[c], red[128 + c]);
    __syncthreads();
    float lsum = 0.f;
    #pragma unroll
    for (int r = 0; r < 32; r++) {
        v[r] = __expf(v[r] - gmx);
        lsum += v[r];
    }
    red[h*128 + c] = lsum;
    __syncthreads();
    float inv = 1.f / (red[c] + red[128 + c]);

    #pragma unroll
    for (int r = 0; r < 32; r++)
        Cs[(h*32 + r)*132 + c] = v[r] * inv;
    __syncthreads();

    // colsum: row = tid>>2, quarter q = tid&3 (32 cols each)
    {
        int row = tid >> 2, q = tid & 3;
        float s = 0.f;
        #pragma unroll
        for (int j = 0; j < 32; j++) s += Cs[row*132 + q*32 + j];
        s += __shfl_xor_sync(0xffffffffu, s, 1);
        s += __shfl_xor_sync(0xffffffffu, s, 2);
        if (q == 0) atomicAdd(&g_colsum[b*64 + row], s);
    }

    __nv_bfloat16* ahp = g_ass_hi + (size_t)b*M*NN;
    __nv_bfloat16* alp = g_ass_lo + (size_t)b*M*NN;
    #pragma unroll
    for (int r = 0; r < 16; r++) {
        int idx = r*256 + tid;
        int m = idx >> 6, c2 = (idx & 63)*2;
        uint32_t hh, ll;
        split2f(Cs[m*132 + c2], Cs[m*132 + c2 + 1], hh, ll);
        *(uint32_t*)&ahp[(size_t)m*NN + n0 + c2] = hh;
        *(uint32_t*)&alp[(size_t)m*NN + n0 + c2] = ll;
    }
}

// ---------------------------------------------------------------------------
// k_av: HMMA + reg-prefetch (exact R14 form: launch_bounds(256,2), rb[8]).
// Atomic accumulation into g_agg. grid (2 dt, 32 s, 8 b).
#define AV_AH 0         // [64][72] bf16
#define AV_AL 9216
#define AV_BH 18432     // [64][136] bf16
#define AV_BL 35840
#define AV_SMEM 53248
__global__ void __launch_bounds__(256, 2) k_av(const float* __restrict__ values) {
    extern __shared__ char dsm[];
    const int tid = threadIdx.x, lane = tid & 31, w = tid >> 5;
    const int dt = blockIdx.x, s = blockIdx.y, b = blockIdx.z;
    const int nb = s * 512, d0t = dt * 128;
    uint32_t sb = smem_to_u32(dsm);

    const __nv_bfloat16* ahp = g_ass_hi + (size_t)b*M*NN;
    const __nv_bfloat16* alp = g_ass_lo + (size_t)b*M*NN;
    const float* vp = values + (size_t)b*NN*D;

    const int m0 = 16*(w & 3);
    const int dh = w >> 2;

    const int am = tid >> 3, ak8 = (tid & 7)*8;      // A: row r*32+am
    const int bk = tid >> 5, bd = 4*(tid & 31);      // B: row r*8+bk

    float C[8][4] = {};
    uint4 rah[2], ral[2];
    float4 rb[8];

    #pragma unroll
    for (int r = 0; r < 2; r++) {
        rah[r] = *(const uint4*)&ahp[(size_t)(r*32 + am)*NN + nb + ak8];
        ral[r] = *(const uint4*)&alp[(size_t)(r*32 + am)*NN + nb + ak8];
    }
    #pragma unroll
    for (int r = 0; r < 8; r++)
        rb[r] = *(const float4*)&vp[(size_t)(nb + r*8 + bk)*D + d0t + bd];

    for (int ci = 0; ci < 8; ci++) {
        __syncthreads();
        #pragma unroll
        for (int r = 0; r < 2; r++) {
            *(uint4*)(dsm + AV_AH + ((r*32 + am)*72 + ak8)*2) = rah[r];
            *(uint4*)(dsm + AV_AL + ((r*32 + am)*72 + ak8)*2) = ral[r];
        }
        #pragma unroll
        for (int r = 0; r < 8; r++) {
            float4 v = rb[r];
            uint32_t h0, l0, h1, l1;
            split2f(v.x, v.y, h0, l0);
            split2f(v.z, v.w, h1, l1);
            *(uint2*)(dsm + AV_BH + ((r*8 + bk)*136 + bd)*2) = make_uint2(h0, h1);
            *(uint2*)(dsm + AV_BL + ((r*8 + bk)*136 + bd)*2) = make_uint2(l0, l1);
        }
        __syncthreads();
        if (ci < 7) {
            int nk = nb + (ci + 1)*64;
            #pragma unroll
            for (int r = 0; r < 2; r++) {
                rah[r] = *(const uint4*)&ahp[(size_t)(r*32 + am)*NN + nk + ak8];
                ral[r] = *(const uint4*)&alp[(size_t)(r*32 + am)*NN + nk + ak8];
            }
            #pragma unroll
            for (int r = 0; r < 8; r++)
                rb[r] = *(const float4*)&vp[(size_t)(nk + r*8 + bk)*D + d0t + bd];
        }
        #pragma unroll
        for (int ks = 0; ks < 4; ks++) {
            uint32_t ah[4], al[4];
            uint32_t aoff = ((m0 + (lane & 15))*72 + ks*16 + 8*(lane >> 4))*2;
            ldsm4(ah, sb + AV_AH + aoff);
            ldsm4(al, sb + AV_AL + aoff);
            #pragma unroll
            for (int g = 0; g < 4; g++) {
                uint32_t bh[4], bl[4];
                uint32_t boff = ((ks*16 + (lane & 15))*136 + dh*64 + g*16 + 8*(lane >> 4))*2;
                ldsm4t(bh, sb + AV_BH + boff);
                ldsm4t(bl, sb + AV_BL + boff);
                mma16816(C[2*g],   ah, bh);
                mma16816(C[2*g],   al, bh);
                mma16816(C[2*g],   ah, bl);
                mma16816(C[2*g+1], ah, bh+2);
                mma16816(C[2*g+1], al, bh+2);
                mma16816(C[2*g+1], ah, bl+2);
            }
        }
    }
    float* op = g_agg + (size_t)b*M*D;
    #pragma unroll
    for (int f = 0; f < 8; f++) {
        int col = d0t + dh*64 + (f>>1)*16 + (f&1)*8 + 2*(lane & 3);
        int row = m0 + (lane >> 2);
        atomicAdd(&op[row*256 + col],     C[f][0]);
        atomicAdd(&op[row*256 + col + 1], C[f][1]);
        atomicAdd(&op[(row+8)*256 + col],     C[f][2]);
        atomicAdd(&op[(row+8)*256 + col + 1], C[f][3]);
    }
}

// ---------------------------------------------------------------------------
__global__ void __launch_bounds__(256) k_agg() {
    int bm = blockIdx.x;
    int b = bm >> 6, m = bm & 63;
    int d = threadIdx.x;
    float val = (g_vc[bm*D + d] + g_agg[bm*D + d]) / (g_colsum[bm] + 1e-7f);
    __nv_bfloat16 h = __float2bfloat16(val);
    __nv_bfloat16 l = __float2bfloat16(val - __bfloat162float(h));
    g_aggT_hi[((size_t)b*D + d)*64 + m] = h;
    g_aggT_lo[((size_t)b*D + d)*64 + m] = l;
}

// ---------------------------------------------------------------------------
// k_x: HMMA. x[128d][128n] = aggT @ assign, K=64 single shot.
// R14 body + direct fragment stores (full-32B-sector float2 quads, no Cs).
// grid (2 dt, 128 n, 8 b).
#define X_AH 0          // [128][72] bf16 = 18432
#define X_AL 18432
#define X_BH 36864      // [64][136] bf16 = 17408
#define X_BL 54272
#define X_SMEM 71680
__global__ void __launch_bounds__(256) k_x(float* __restrict__ x) {
    extern __shared__ char dsm[];
    const int tid = threadIdx.x, lane = tid & 31, w = tid >> 5;
    const int d0 = blockIdx.x * 128, n0 = blockIdx.y * 128, b = blockIdx.z;
    uint32_t sb = smem_to_u32(dsm);

    #pragma unroll
    for (int r = 0; r < 4; r++) {
        int idx = r*256 + tid;
        int d = idx >> 3, m8 = (idx & 7)*8;
        size_t src = ((size_t)b*D + d0 + d)*64 + m8;
        *(uint4*)(dsm + X_AH + (d*72 + m8)*2) = *(const uint4*)&g_aggT_hi[src];
        *(uint4*)(dsm + X_AL + (d*72 + m8)*2) = *(const uint4*)&g_aggT_lo[src];
    }
    #pragma unroll
    for (int r = 0; r < 4; r++) {
        int idx = r*256 + tid;
        int m = idx >> 4, n8 = (idx & 15)*8;
        size_t src = (size_t)(b*M + m)*NN + n0 + n8;
        *(uint4*)(dsm + X_BH + (m*136 + n8)*2) = *(const uint4*)&g_ass_hi[src];
        *(uint4*)(dsm + X_BL + (m*136 + n8)*2) = *(const uint4*)&g_ass_lo[src];
    }
    __syncthreads();

    const int d0w = 16*w;
    float C[16][4] = {};
    #pragma unroll
    for (int ks = 0; ks < 4; ks++) {
        uint32_t ah[4], al[4];
        uint32_t aoff = ((d0w + (lane & 15))*72 + ks*16 + 8*(lane >> 4))*2;
        ldsm4(ah, sb + X_AH + aoff);
        ldsm4(al, sb + X_AL + aoff);
        #pragma unroll
        for (int g = 0; g < 8; g++) {
            uint32_t bh[4], bl[4];
            uint32_t boff = ((ks*16 + (lane & 15))*136 + g*16 + 8*(lane >> 4))*2;
            ldsm4t(bh, sb + X_BH + boff);
            ldsm4t(bl, sb + X_BL + boff);
            mma16816(C[2*g],   ah, bh);
            mma16816(C[2*g],   al, bh);
            mma16816(C[2*g],   ah, bl);
            mma16816(C[2*g+1], ah, bh+2);
            mma16816(C[2*g+1], al, bh+2);
            mma16816(C[2*g+1], ah, bl+2);
        }
    }

    // direct stores: each 4-lane quad writes a full 32B sector per row
    #pragma unroll
    for (int f = 0; f < 16; f++) {
        int col = n0 + (f>>1)*16 + (f&1)*8 + 2*(lane & 3);
        int row = d0 + d0w + (lane >> 2);
        float* xp = x + (size_t)(b*D + row)*NN + col;
        *(float2*)xp = make_float2(C[f][0], C[f][1]);
        *(float2*)(xp + 8*NN) = make_float2(C[f][2], C[f][3]);
    }
}

// ---------------------------------------------------------------------------
extern "C" void kernel_launch(void* const* d_in, const int* in_sizes, int n_in,
                              void* d_out, int out_size) {
    const float* points    = (const float*)d_in[0];
    const float* clusters  = (const float*)d_in[1];
    const float* values    = (const float*)d_in[2];
    const float* vclusters = (const float*)d_in[3];
    const float* alpha     = (const float*)d_in[4];
    const float* beta      = (const float*)d_in[5];
    const float* cbias     = (const float*)d_in[6];
    const float* Wc        = (const float*)d_in[7];
    const float* bc        = (const float*)d_in[8];
    const float* vbias     = (const float*)d_in[9];
    const float* Wv        = (const float*)d_in[10];
    const float* bv        = (const float*)d_in[11];
    float* x = (float*)d_out;

    cudaFuncSetAttribute(k_sim, cudaFuncAttributeMaxDynamicSharedMemorySize, SIM_SMEM);
    cudaFuncSetAttribute(k_av,  cudaFuncAttributeMaxDynamicSharedMemorySize, AV_SMEM);
    cudaFuncSetAttribute(k_x,   cudaFuncAttributeMaxDynamicSharedMemorySize, X_SMEM);

    k_init<<<512, 256>>>();
    k_prep<<<dim3(4, 8, 2), 256>>>(clusters, cbias, Wc, bc,
                                   vclusters, vbias, Wv, bv);
    k_norm<<<512, 256>>>(alpha);
    k_sim<<<dim3(NN/128, B), 256, SIM_SMEM>>>(points, beta);
    k_av<<<dim3(2, AV_SPLITS, B), 256, AV_SMEM>>>(values);
    k_agg<<<512, 256>>>();
    k_x<<<dim3(2, NN/128, B), 256, X_SMEM>>>(x);
}